// round 8
// baseline (speedup 1.0000x reference)
#include <cuda_runtime.h>
#include <math.h>
#include <stdint.h>

#define N_INST 4096
#define LF 500
#define KPAD 512
#define CC 5

// ---------------- scratch (device globals; no allocation) ----------------
__device__ __align__(128) float g_P1[N_INST*2880];
__device__ __align__(128) float g_P2[N_INST*800];
__device__ __align__(128) float g_H [N_INST*LF];
__device__ __align__(128) float g_Hhi[N_INST*KPAD];
__device__ __align__(128) float g_Hlo[N_INST*KPAD];
__device__ __align__(128) float g_d2[(size_t)N_INST*N_INST];   // also conv2 scratch (262144 x 64)
__device__ __align__(128) float g_AH[N_INST*LF];
__device__ __align__(128) float g_Zl[N_INST*LF];
__device__ float g_S [N_INST*CC];
__device__ float g_AS[N_INST*CC];
__device__ float g_sq[N_INST];
__device__ float g_rs[N_INST];    // 1/max(deg,1)
__device__ float g_rs1[N_INST];   // 1/(deg+1)
__device__ int   g_degi[N_INST];
__device__ int   g_rowptr[N_INST+1];
__device__ int   g_idx[(size_t)N_INST*N_INST];   // CSR col indices (worst case)
__device__ unsigned int g_hist[128];
__device__ float g_thr2[1];
__device__ float g_bnsum[LF], g_bnsq[LF], g_bna[LF], g_bnbs[LF];
__device__ float g_coar[CC*LF], g_neigh[CC*LF], g_E[CC*LF], g_pooled[CC*LF];
__device__ float g_Ac[CC*CC], g_Mc[CC*CC], g_invdegc[CC];

// ---------------- init ----------------
__global__ void init_kernel() {
    int t = threadIdx.x;
    for (int i = t; i < 128; i += 512) g_hist[i] = 0u;
    for (int i = t; i < LF; i += 512) { g_bnsum[i] = 0.f; g_bnsq[i] = 0.f; }
}

// ---------------- conv1 + relu + maxpool: [N,1,28,28] -> [N,20,12,12] ----------------
__global__ __launch_bounds__(512) void conv1_kernel(const float* __restrict__ x,
    const float* __restrict__ w, const float* __restrict__ b) {
    __shared__ float simg[784];
    __shared__ float sw[500];
    __shared__ float sb[20];
    int n = blockIdx.x;
    int tid = threadIdx.x;
    const float* img = x + n * 784;
    for (int i = tid; i < 784; i += 512) simg[i] = img[i];
    for (int i = tid; i < 500; i += 512) sw[i] = w[i];
    if (tid < 20) sb[tid] = b[tid];
    __syncthreads();
    if (tid < 480) {
        int ch = tid / 24;
        int rem = tid % 24;
        int py = rem / 2;
        int half = rem % 2;
        int cx0 = half * 12;
        float acc0[12], acc1[12];
        #pragma unroll
        for (int xx = 0; xx < 12; xx++) { acc0[xx] = 0.f; acc1[xx] = 0.f; }
        const float* wch = &sw[ch * 25];
        int ry0 = 2 * py;
        for (int ki = 0; ki < 5; ki++) {
            float in0[16], in1[16];
            const float* r0 = &simg[(ry0 + ki) * 28 + cx0];
            const float* r1 = &simg[(ry0 + ki + 1) * 28 + cx0];
            #pragma unroll
            for (int t2 = 0; t2 < 16; t2++) { in0[t2] = r0[t2]; in1[t2] = r1[t2]; }
            #pragma unroll
            for (int kj = 0; kj < 5; kj++) {
                float wv = wch[ki * 5 + kj];
                #pragma unroll
                for (int xx = 0; xx < 12; xx++) {
                    acc0[xx] += in0[xx + kj] * wv;
                    acc1[xx] += in1[xx + kj] * wv;
                }
            }
        }
        float bv = sb[ch];
        float* outp = &g_P1[n * 2880 + ch * 144 + py * 12 + half * 6];
        #pragma unroll
        for (int px = 0; px < 6; px++) {
            float m = fmaxf(fmaxf(acc0[2*px], acc0[2*px+1]), fmaxf(acc1[2*px], acc1[2*px+1]));
            outp[px] = fmaxf(m + bv, 0.f);
        }
    }
}

// ---------------- shared mma helpers ----------------
#define GSTRIDE 36
#define GRAM_SMEM (4 * 128 * GSTRIDE * 4)     // 73728 B

__device__ __forceinline__ void mma_tf32(float* c, const uint32_t* a, uint32_t b0, uint32_t b1) {
    asm volatile(
        "mma.sync.aligned.m16n8k8.row.col.f32.tf32.tf32.f32 "
        "{%0,%1,%2,%3}, {%4,%5,%6,%7}, {%8,%9}, {%0,%1,%2,%3};\n"
        : "+f"(c[0]), "+f"(c[1]), "+f"(c[2]), "+f"(c[3])
        : "r"(a[0]), "r"(a[1]), "r"(a[2]), "r"(a[3]), "r"(b0), "r"(b1));
}

__device__ __forceinline__ void tf32_split(float v, float& hi, float& lo) {
    uint32_t h = __float_as_uint(v) & 0xFFFFE000u;
    float hf = __uint_as_float(h);
    float lf = v - hf;
    uint32_t l;
    asm("cvt.rna.tf32.f32 %0, %1;" : "=r"(l) : "f"(lf));
    hi = hf;
    lo = __uint_as_float(l);
}

// ---------------- conv2 as implicit GEMM (3xTF32 mma) ----------------
// out[row=n*64+oy*8+ox, oc] = sum_k P1[n, ic, (oy+ki)*12 + (ox+kj)] * w2[oc, k]
// M = 262144 (2048 tiles of 128), N-tile = 64 (oc<50 live), K = 500 (16 chunks of 32).
// Writes conv result to g_d2 scratch, [row*64 + oc].
#define C2_SMEM ((128 * GSTRIDE * 2 + 64 * GSTRIDE * 2) * 4)   // 55296 B

__global__ __launch_bounds__(256) void conv2_mma_kernel(const float* __restrict__ w) {
    extern __shared__ float smem[];
    float* sAhi = smem;
    float* sAlo = sAhi + 128 * GSTRIDE;
    float* sBhi = sAlo + 128 * GSTRIDE;
    float* sBlo = sBhi + 64 * GSTRIDE;

    int m0 = blockIdx.x * 128;
    int tid = threadIdx.x;
    int lane = tid & 31, wid = tid >> 5;
    int warp_m = wid & 3, warp_n = wid >> 2;
    int group = lane >> 2, tid4 = lane & 3;

    float acc[2][4][4];
    #pragma unroll
    for (int mt = 0; mt < 2; mt++)
        #pragma unroll
        for (int nt = 0; nt < 4; nt++)
            #pragma unroll
            for (int q = 0; q < 4; q++) acc[mt][nt][q] = 0.f;

    for (int kc = 0; kc < 16; kc++) {
        // ---- A: im2col gather, 128 rows x 32 k ----
        #pragma unroll
        for (int t = 0; t < 4; t++) {
            int id = tid + 256 * t;              // 0..1023
            int row = id >> 3, c4 = id & 7;
            int gr = m0 + row;
            int n = gr >> 6;
            int pos = gr & 63;
            int oy = pos >> 3, ox = pos & 7;
            int kb = kc * 32 + c4 * 4;
            const float* p1n = g_P1 + (size_t)n * 2880;
            float v[4];
            #pragma unroll
            for (int j = 0; j < 4; j++) {
                int k = kb + j;
                float xv = 0.f;
                if (k < 500) {
                    int ic = k / 25;
                    int rem = k - ic * 25;
                    int ki = rem / 5;
                    int kj = rem - ki * 5;
                    xv = p1n[ic * 144 + (oy + ki) * 12 + ox + kj];
                }
                v[j] = xv;
            }
            int soff = row * GSTRIDE + c4 * 4;
            #pragma unroll
            for (int j = 0; j < 4; j++) {
                float hi, lo;
                tf32_split(v[j], hi, lo);
                sAhi[soff + j] = hi;
                sAlo[soff + j] = lo;
            }
        }
        // ---- B: weights, 64 rows x 32 k ----
        #pragma unroll
        for (int t = 0; t < 2; t++) {
            int id = tid + 256 * t;              // 0..511
            int row = id >> 3, c4 = id & 7;
            int kb = kc * 32 + c4 * 4;
            float v[4] = {0.f, 0.f, 0.f, 0.f};
            if (row < 50) {
                #pragma unroll
                for (int j = 0; j < 4; j++) {
                    int k = kb + j;
                    if (k < 500) v[j] = w[row * 500 + k];
                }
            }
            int soff = row * GSTRIDE + c4 * 4;
            #pragma unroll
            for (int j = 0; j < 4; j++) {
                float hi, lo;
                tf32_split(v[j], hi, lo);
                sBhi[soff + j] = hi;
                sBlo[soff + j] = lo;
            }
        }
        __syncthreads();
        #pragma unroll
        for (int ks = 0; ks < 4; ks++) {
            int k0 = ks * 8;
            uint32_t ahi[2][4], alo[2][4];
            #pragma unroll
            for (int mt = 0; mt < 2; mt++) {
                int r0 = (warp_m * 32 + mt * 16 + group) * GSTRIDE;
                int r8 = r0 + 8 * GSTRIDE;
                ahi[mt][0] = __float_as_uint(sAhi[r0 + k0 + tid4]);
                ahi[mt][1] = __float_as_uint(sAhi[r8 + k0 + tid4]);
                ahi[mt][2] = __float_as_uint(sAhi[r0 + k0 + tid4 + 4]);
                ahi[mt][3] = __float_as_uint(sAhi[r8 + k0 + tid4 + 4]);
                alo[mt][0] = __float_as_uint(sAlo[r0 + k0 + tid4]);
                alo[mt][1] = __float_as_uint(sAlo[r8 + k0 + tid4]);
                alo[mt][2] = __float_as_uint(sAlo[r0 + k0 + tid4 + 4]);
                alo[mt][3] = __float_as_uint(sAlo[r8 + k0 + tid4 + 4]);
            }
            #pragma unroll
            for (int nt = 0; nt < 4; nt++) {
                int nb = (warp_n * 32 + nt * 8 + group) * GSTRIDE;
                uint32_t bhi0 = __float_as_uint(sBhi[nb + k0 + tid4]);
                uint32_t bhi1 = __float_as_uint(sBhi[nb + k0 + tid4 + 4]);
                uint32_t blo0 = __float_as_uint(sBlo[nb + k0 + tid4]);
                uint32_t blo1 = __float_as_uint(sBlo[nb + k0 + tid4 + 4]);
                #pragma unroll
                for (int mt = 0; mt < 2; mt++) {
                    mma_tf32(acc[mt][nt], ahi[mt], bhi0, bhi1);
                    mma_tf32(acc[mt][nt], ahi[mt], blo0, blo1);
                    mma_tf32(acc[mt][nt], alo[mt], bhi0, bhi1);
                }
            }
        }
        __syncthreads();
    }

    // epilogue: raw conv values to scratch [row*64 + oc]
    float* scratch = g_d2;
    #pragma unroll
    for (int mt = 0; mt < 2; mt++) {
        int gm0 = m0 + warp_m * 32 + mt * 16 + group;
        int gm8 = gm0 + 8;
        #pragma unroll
        for (int nt = 0; nt < 4; nt++) {
            int gn = warp_n * 32 + nt * 8 + 2 * tid4;
            *(float2*)&scratch[(size_t)gm0 * 64 + gn] = make_float2(acc[mt][nt][0], acc[mt][nt][1]);
            *(float2*)&scratch[(size_t)gm8 * 64 + gn] = make_float2(acc[mt][nt][2], acc[mt][nt][3]);
        }
    }
}

// ---------------- conv2 pool: bias + relu + 2x2 maxpool -> g_P2 ----------------
__global__ __launch_bounds__(256) void pool2_kernel(const float* __restrict__ b) {
    __shared__ float s[4096];
    int n = blockIdx.x;
    int tid = threadIdx.x;
    const float4* src = (const float4*)(g_d2 + (size_t)n * 4096);
    for (int i = tid; i < 1024; i += 256) ((float4*)s)[i] = src[i];
    __syncthreads();
    for (int idx = tid; idx < 800; idx += 256) {
        int oc = idx >> 4;         // idx/16
        int p = idx & 15;
        int py = p >> 2, px = p & 3;
        int pos0 = (2 * py) * 8 + 2 * px;
        float m = fmaxf(fmaxf(s[pos0 * 64 + oc], s[(pos0 + 1) * 64 + oc]),
                        fmaxf(s[(pos0 + 8) * 64 + oc], s[(pos0 + 9) * 64 + oc]));
        g_P2[n * 800 + idx] = fmaxf(m + b[oc], 0.f);
    }
}

// ---------------- double-buffered SGEMM: C[M,N] = A[M,K] @ B[N,K]^T ----------------
template<bool ROWSCALE, bool ACCUM, bool HASBIAS, int ACT>
__global__ __launch_bounds__(256) void sgemm_tb(
    const float* __restrict__ A, const float* __restrict__ B, float* __restrict__ C,
    int M, int N, int K, int lda, int ldb, int ldc,
    const float* __restrict__ bias, const float* __restrict__ rowscale) {
    __shared__ float As[2][8][128];
    __shared__ float Bs[2][8][128];
    int m0 = blockIdx.y * 128, n0 = blockIdx.x * 128;
    int tid = threadIdx.x;
    int tx = tid & 15, ty = tid >> 4;
    int arow = tid >> 1, acol = (tid & 1) * 4;

    float acc[8][8];
    #pragma unroll
    for (int i = 0; i < 8; i++)
        #pragma unroll
        for (int j = 0; j < 8; j++) acc[i][j] = 0.f;

    auto loadA = [&](int k0, float4& v) {
        int gm = m0 + arow, gk = k0 + acol;
        if (gm < M && gk + 3 < K) {
            v = *(const float4*)(A + (size_t)gm * lda + gk);
        } else {
            v.x = (gm < M && gk     < K) ? A[(size_t)gm * lda + gk    ] : 0.f;
            v.y = (gm < M && gk + 1 < K) ? A[(size_t)gm * lda + gk + 1] : 0.f;
            v.z = (gm < M && gk + 2 < K) ? A[(size_t)gm * lda + gk + 2] : 0.f;
            v.w = (gm < M && gk + 3 < K) ? A[(size_t)gm * lda + gk + 3] : 0.f;
        }
        if (ROWSCALE) {
            float r = (gm < M) ? rowscale[gm] : 1.f;
            v.x *= r; v.y *= r; v.z *= r; v.w *= r;
        }
    };
    auto loadB = [&](int k0, float4& v) {
        int gn = n0 + arow, gk = k0 + acol;
        if (gn < N && gk + 3 < K) {
            v = *(const float4*)(B + (size_t)gn * ldb + gk);
        } else {
            v.x = (gn < N && gk     < K) ? B[(size_t)gn * ldb + gk    ] : 0.f;
            v.y = (gn < N && gk + 1 < K) ? B[(size_t)gn * ldb + gk + 1] : 0.f;
            v.z = (gn < N && gk + 2 < K) ? B[(size_t)gn * ldb + gk + 2] : 0.f;
            v.w = (gn < N && gk + 3 < K) ? B[(size_t)gn * ldb + gk + 3] : 0.f;
        }
    };
    auto store = [&](int buf, const float4& av, const float4& bv) {
        As[buf][acol + 0][arow] = av.x;
        As[buf][acol + 1][arow] = av.y;
        As[buf][acol + 2][arow] = av.z;
        As[buf][acol + 3][arow] = av.w;
        Bs[buf][acol + 0][arow] = bv.x;
        Bs[buf][acol + 1][arow] = bv.y;
        Bs[buf][acol + 2][arow] = bv.z;
        Bs[buf][acol + 3][arow] = bv.w;
    };

    {
        float4 av, bv;
        loadA(0, av); loadB(0, bv);
        store(0, av, bv);
    }
    __syncthreads();
    int nk = (K + 7) >> 3;
    for (int t = 0; t < nk; t++) {
        int buf = t & 1;
        float4 nav, nbv;
        bool more = (t + 1 < nk);
        if (more) { loadA((t + 1) * 8, nav); loadB((t + 1) * 8, nbv); }
        #pragma unroll
        for (int kk = 0; kk < 8; kk++) {
            float4 a0 = *(const float4*)&As[buf][kk][ty * 4];
            float4 a1 = *(const float4*)&As[buf][kk][64 + ty * 4];
            float4 b0 = *(const float4*)&Bs[buf][kk][tx * 4];
            float4 b1 = *(const float4*)&Bs[buf][kk][64 + tx * 4];
            float ar[8] = {a0.x,a0.y,a0.z,a0.w,a1.x,a1.y,a1.z,a1.w};
            float br[8] = {b0.x,b0.y,b0.z,b0.w,b1.x,b1.y,b1.z,b1.w};
            #pragma unroll
            for (int i = 0; i < 8; i++)
                #pragma unroll
                for (int j = 0; j < 8; j++)
                    acc[i][j] += ar[i] * br[j];
        }
        if (more) {
            store(buf ^ 1, nav, nbv);
            __syncthreads();
        }
    }

    #pragma unroll
    for (int i = 0; i < 8; i++) {
        int gm = m0 + ((i < 4) ? (ty * 4 + i) : (64 + ty * 4 + i - 4));
        if (gm >= M) continue;
        #pragma unroll
        for (int j = 0; j < 8; j++) {
            int gn = n0 + ((j < 4) ? (tx * 4 + j) : (64 + tx * 4 + j - 4));
            if (gn >= N) continue;
            float v = acc[i][j];
            if (ACCUM) v += C[(size_t)gm * ldc + gn];
            if (HASBIAS) v += bias[gn];
            if (ACT == 1) v = fmaxf(v, 0.f);
            else if (ACT == 2) v = v > 0.f ? v : 0.01f * v;
            C[(size_t)gm * ldc + gn] = v;
        }
    }
}

// ---------------- generic 3xTF32 mma GEMM (dual): C = A1@B1^T + A2@B2^T ----------------
template<bool DUAL, bool ROWSCALE, bool HASBIAS, int ACT>
__global__ __launch_bounds__(256) void gemm_mma(
    const float* __restrict__ A1, const float* __restrict__ B1,
    const float* __restrict__ A2, const float* __restrict__ B2,
    float* __restrict__ C, int M, int N, int K,
    int lda, int ldb, int ldc,
    const float* __restrict__ bias, const float* __restrict__ rowscale) {
    extern __shared__ float smem[];
    float* sAhi = smem;
    float* sAlo = smem + 128 * GSTRIDE;
    float* sBhi = smem + 2 * 128 * GSTRIDE;
    float* sBlo = smem + 3 * 128 * GSTRIDE;

    int m0 = blockIdx.y * 128, n0 = blockIdx.x * 128;
    int tid = threadIdx.x;
    int lane = tid & 31, wid = tid >> 5;
    int warp_m = wid & 3, warp_n = wid >> 2;
    int group = lane >> 2, tid4 = lane & 3;

    float acc[2][8][4];
    #pragma unroll
    for (int mt = 0; mt < 2; mt++)
        #pragma unroll
        for (int nt = 0; nt < 8; nt++)
            #pragma unroll
            for (int q = 0; q < 4; q++) acc[mt][nt][q] = 0.f;

    int nkc = (K + 31) >> 5;
    int npair = DUAL ? 2 : 1;
    for (int p = 0; p < npair; p++) {
        const float* A = (DUAL && p) ? A2 : A1;
        const float* B = (DUAL && p) ? B2 : B1;
        for (int kc = 0; kc < nkc; kc++) {
            #pragma unroll
            for (int t = 0; t < 4; t++) {
                int id = tid + 256 * t;          // 0..1023
                int row = id >> 3, c4 = id & 7;
                int gk = kc * 32 + c4 * 4;
                int soff = row * GSTRIDE + c4 * 4;
                {
                    int gm = m0 + row;
                    float4 v = make_float4(0.f, 0.f, 0.f, 0.f);
                    if (gm < M) {
                        if (gk + 3 < K) {
                            v = *(const float4*)(A + (size_t)gm * lda + gk);
                        } else {
                            if (gk     < K) v.x = A[(size_t)gm * lda + gk    ];
                            if (gk + 1 < K) v.y = A[(size_t)gm * lda + gk + 1];
                            if (gk + 2 < K) v.z = A[(size_t)gm * lda + gk + 2];
                            if (gk + 3 < K) v.w = A[(size_t)gm * lda + gk + 3];
                        }
                        if (ROWSCALE && p == 0) {
                            float r = rowscale[gm];
                            v.x *= r; v.y *= r; v.z *= r; v.w *= r;
                        }
                    }
                    float hx, lx, hy, ly, hz, lz, hw, lw;
                    tf32_split(v.x, hx, lx); tf32_split(v.y, hy, ly);
                    tf32_split(v.z, hz, lz); tf32_split(v.w, hw, lw);
                    sAhi[soff] = hx; sAhi[soff+1] = hy; sAhi[soff+2] = hz; sAhi[soff+3] = hw;
                    sAlo[soff] = lx; sAlo[soff+1] = ly; sAlo[soff+2] = lz; sAlo[soff+3] = lw;
                }
                {
                    int gn = n0 + row;
                    float4 v = make_float4(0.f, 0.f, 0.f, 0.f);
                    if (gn < N) {
                        if (gk + 3 < K) {
                            v = *(const float4*)(B + (size_t)gn * ldb + gk);
                        } else {
                            if (gk     < K) v.x = B[(size_t)gn * ldb + gk    ];
                            if (gk + 1 < K) v.y = B[(size_t)gn * ldb + gk + 1];
                            if (gk + 2 < K) v.z = B[(size_t)gn * ldb + gk + 2];
                            if (gk + 3 < K) v.w = B[(size_t)gn * ldb + gk + 3];
                        }
                    }
                    float hx, lx, hy, ly, hz, lz, hw, lw;
                    tf32_split(v.x, hx, lx); tf32_split(v.y, hy, ly);
                    tf32_split(v.z, hz, lz); tf32_split(v.w, hw, lw);
                    sBhi[soff] = hx; sBhi[soff+1] = hy; sBhi[soff+2] = hz; sBhi[soff+3] = hw;
                    sBlo[soff] = lx; sBlo[soff+1] = ly; sBlo[soff+2] = lz; sBlo[soff+3] = lw;
                }
            }
            __syncthreads();
            #pragma unroll
            for (int ks = 0; ks < 4; ks++) {
                int k0 = ks * 8;
                uint32_t ahi[2][4], alo[2][4];
                #pragma unroll
                for (int mt = 0; mt < 2; mt++) {
                    int r0 = (warp_m * 32 + mt * 16 + group) * GSTRIDE;
                    int r8 = r0 + 8 * GSTRIDE;
                    ahi[mt][0] = __float_as_uint(sAhi[r0 + k0 + tid4]);
                    ahi[mt][1] = __float_as_uint(sAhi[r8 + k0 + tid4]);
                    ahi[mt][2] = __float_as_uint(sAhi[r0 + k0 + tid4 + 4]);
                    ahi[mt][3] = __float_as_uint(sAhi[r8 + k0 + tid4 + 4]);
                    alo[mt][0] = __float_as_uint(sAlo[r0 + k0 + tid4]);
                    alo[mt][1] = __float_as_uint(sAlo[r8 + k0 + tid4]);
                    alo[mt][2] = __float_as_uint(sAlo[r0 + k0 + tid4 + 4]);
                    alo[mt][3] = __float_as_uint(sAlo[r8 + k0 + tid4 + 4]);
                }
                #pragma unroll
                for (int nt = 0; nt < 8; nt++) {
                    int nb = (warp_n * 64 + nt * 8 + group) * GSTRIDE;
                    uint32_t bhi0 = __float_as_uint(sBhi[nb + k0 + tid4]);
                    uint32_t bhi1 = __float_as_uint(sBhi[nb + k0 + tid4 + 4]);
                    uint32_t blo0 = __float_as_uint(sBlo[nb + k0 + tid4]);
                    uint32_t blo1 = __float_as_uint(sBlo[nb + k0 + tid4 + 4]);
                    #pragma unroll
                    for (int mt = 0; mt < 2; mt++) {
                        mma_tf32(acc[mt][nt], ahi[mt], bhi0, bhi1);
                        mma_tf32(acc[mt][nt], ahi[mt], blo0, blo1);
                        mma_tf32(acc[mt][nt], alo[mt], bhi0, bhi1);
                    }
                }
            }
            __syncthreads();
        }
    }

    #pragma unroll
    for (int mt = 0; mt < 2; mt++) {
        int gm0 = m0 + warp_m * 32 + mt * 16 + group;
        int gm8 = gm0 + 8;
        #pragma unroll
        for (int nt = 0; nt < 8; nt++) {
            int gn = n0 + warp_n * 64 + nt * 8 + 2 * tid4;
            #pragma unroll
            for (int q = 0; q < 2; q++) {
                int gnn = gn + q;
                if (gnn >= N) continue;
                float bv = HASBIAS ? bias[gnn] : 0.f;
                if (gm0 < M) {
                    float v = acc[mt][nt][q] + bv;
                    if (ACT == 1) v = fmaxf(v, 0.f);
                    else if (ACT == 2) v = v > 0.f ? v : 0.01f * v;
                    C[(size_t)gm0 * ldc + gnn] = v;
                }
                if (gm8 < M) {
                    float v = acc[mt][nt][2 + q] + bv;
                    if (ACT == 1) v = fmaxf(v, 0.f);
                    else if (ACT == 2) v = v > 0.f ? v : 0.01f * v;
                    C[(size_t)gm8 * ldc + gnn] = v;
                }
            }
        }
    }
}

// ---------------- split H into tf32 hi/lo, padded to KPAD (for gram) ----------------
__global__ __launch_bounds__(256) void split_kernel() {
    int idx = blockIdx.x * 256 + threadIdx.x;      // float4 index
    if (idx >= N_INST * (KPAD / 4)) return;
    int row = idx >> 7;          // KPAD/4 = 128
    int c4  = idx & 127;
    float4 hi, lo;
    if (c4 < 125) {
        float4 v = *(const float4*)(g_H + (size_t)row * LF + c4 * 4);
        tf32_split(v.x, hi.x, lo.x);
        tf32_split(v.y, hi.y, lo.y);
        tf32_split(v.z, hi.z, lo.z);
        tf32_split(v.w, hi.w, lo.w);
    } else {
        hi = make_float4(0.f, 0.f, 0.f, 0.f);
        lo = hi;
    }
    ((float4*)g_Hhi)[idx] = hi;
    ((float4*)g_Hlo)[idx] = lo;
}

// ---------------- row squared norms ----------------
__global__ __launch_bounds__(256) void sq_kernel() {
    int warp = (blockIdx.x * 256 + threadIdx.x) >> 5;
    int lane = threadIdx.x & 31;
    if (warp >= N_INST) return;
    const float* h = &g_H[warp * LF];
    float s = 0.f;
    for (int k = lane; k < LF; k += 32) { float v = h[k]; s += v * v; }
    #pragma unroll
    for (int o = 16; o > 0; o >>= 1) s += __shfl_xor_sync(0xffffffffu, s, o);
    if (!lane) g_sq[warp] = s;
}

// ---------------- 3xTF32 mma.sync Gram: d2 = sq_i + sq_j - 2*H H^T ----------------
__global__ __launch_bounds__(256) void gram_mma_kernel() {
    extern __shared__ float smem[];
    int m0 = blockIdx.y * 128, n0 = blockIdx.x * 128;
    if (m0 > n0) return;
    float* sAhi = smem;
    float* sAlo = smem + 128 * GSTRIDE;
    float* sBhi = smem + 2 * 128 * GSTRIDE;
    float* sBlo = smem + 3 * 128 * GSTRIDE;

    int tid = threadIdx.x;
    int lane = tid & 31, wid = tid >> 5;
    int warp_m = wid & 3, warp_n = wid >> 2;
    int group = lane >> 2, tid4 = lane & 3;

    float acc[2][8][4];
    #pragma unroll
    for (int mt = 0; mt < 2; mt++)
        #pragma unroll
        for (int nt = 0; nt < 8; nt++)
            #pragma unroll
            for (int q = 0; q < 4; q++) acc[mt][nt][q] = 0.f;

    const float* gAhi = g_Hhi + (size_t)m0 * KPAD;
    const float* gAlo = g_Hlo + (size_t)m0 * KPAD;
    const float* gBhi = g_Hhi + (size_t)n0 * KPAD;
    const float* gBlo = g_Hlo + (size_t)n0 * KPAD;

    for (int kc = 0; kc < KPAD / 32; kc++) {
        #pragma unroll
        for (int t = 0; t < 4; t++) {
            int id = tid + 256 * t;          // 0..1023
            int row = id >> 3, c4 = id & 7;
            size_t goff = (size_t)row * KPAD + kc * 32 + c4 * 4;
            int soff = row * GSTRIDE + c4 * 4;
            *(float4*)(sAhi + soff) = *(const float4*)(gAhi + goff);
            *(float4*)(sAlo + soff) = *(const float4*)(gAlo + goff);
            *(float4*)(sBhi + soff) = *(const float4*)(gBhi + goff);
            *(float4*)(sBlo + soff) = *(const float4*)(gBlo + goff);
        }
        __syncthreads();
        #pragma unroll
        for (int ks = 0; ks < 4; ks++) {
            int k0 = ks * 8;
            uint32_t ahi[2][4], alo[2][4];
            #pragma unroll
            for (int mt = 0; mt < 2; mt++) {
                int r0 = (warp_m * 32 + mt * 16 + group) * GSTRIDE;
                int r8 = r0 + 8 * GSTRIDE;
                ahi[mt][0] = __float_as_uint(sAhi[r0 + k0 + tid4]);
                ahi[mt][1] = __float_as_uint(sAhi[r8 + k0 + tid4]);
                ahi[mt][2] = __float_as_uint(sAhi[r0 + k0 + tid4 + 4]);
                ahi[mt][3] = __float_as_uint(sAhi[r8 + k0 + tid4 + 4]);
                alo[mt][0] = __float_as_uint(sAlo[r0 + k0 + tid4]);
                alo[mt][1] = __float_as_uint(sAlo[r8 + k0 + tid4]);
                alo[mt][2] = __float_as_uint(sAlo[r0 + k0 + tid4 + 4]);
                alo[mt][3] = __float_as_uint(sAlo[r8 + k0 + tid4 + 4]);
            }
            #pragma unroll
            for (int nt = 0; nt < 8; nt++) {
                int nb = (warp_n * 64 + nt * 8 + group) * GSTRIDE;
                uint32_t bhi0 = __float_as_uint(sBhi[nb + k0 + tid4]);
                uint32_t bhi1 = __float_as_uint(sBhi[nb + k0 + tid4 + 4]);
                uint32_t blo0 = __float_as_uint(sBlo[nb + k0 + tid4]);
                uint32_t blo1 = __float_as_uint(sBlo[nb + k0 + tid4 + 4]);
                #pragma unroll
                for (int mt = 0; mt < 2; mt++) {
                    mma_tf32(acc[mt][nt], ahi[mt], bhi0, bhi1);
                    mma_tf32(acc[mt][nt], ahi[mt], blo0, blo1);
                    mma_tf32(acc[mt][nt], alo[mt], bhi0, bhi1);
                }
            }
        }
        __syncthreads();
    }

    float* trans = smem;   // [128 n][stride 129 m]
    #pragma unroll
    for (int mt = 0; mt < 2; mt++) {
        int lm0 = warp_m * 32 + mt * 16 + group;
        int lm8 = lm0 + 8;
        float sq0 = g_sq[m0 + lm0], sq8 = g_sq[m0 + lm8];
        #pragma unroll
        for (int nt = 0; nt < 8; nt++) {
            int ln = warp_n * 64 + nt * 8 + 2 * tid4;
            float sqa = g_sq[n0 + ln], sqb = g_sq[n0 + ln + 1];
            float v00 = sq0 + sqa - 2.f * acc[mt][nt][0];
            float v01 = sq0 + sqb - 2.f * acc[mt][nt][1];
            float v80 = sq8 + sqa - 2.f * acc[mt][nt][2];
            float v81 = sq8 + sqb - 2.f * acc[mt][nt][3];
            *(float2*)&g_d2[(size_t)(m0 + lm0) * N_INST + n0 + ln] = make_float2(v00, v01);
            *(float2*)&g_d2[(size_t)(m0 + lm8) * N_INST + n0 + ln] = make_float2(v80, v81);
            trans[ln * 129 + lm0] = v00;
            trans[(ln + 1) * 129 + lm0] = v01;
            trans[ln * 129 + lm8] = v80;
            trans[(ln + 1) * 129 + lm8] = v81;
        }
    }
    __syncthreads();
    #pragma unroll
    for (int t = 0; t < 4; t++) {
        int id = tid + 256 * t;              // 0..1023
        int n = id >> 3, c4 = id & 7;
        #pragma unroll
        for (int rep = 0; rep < 4; rep++) {
            int cc4 = c4 + rep * 8;          // 0..31
            float4 v;
            v.x = trans[n * 129 + cc4 * 4 + 0];
            v.y = trans[n * 129 + cc4 * 4 + 1];
            v.z = trans[n * 129 + cc4 * 4 + 2];
            v.w = trans[n * 129 + cc4 * 4 + 3];
            *(float4*)&g_d2[(size_t)(n0 + n) * N_INST + m0 + cc4 * 4] = v;
        }
    }
}

// ---------------- distance histogram (upper triangle x2, per-warp smem) ----------------
__global__ __launch_bounds__(256) void hist_kernel() {
    __shared__ unsigned int h[8][128];
    int tid = threadIdx.x, w = tid >> 5;
    for (int i = tid; i < 1024; i += 256) ((unsigned int*)h)[i] = 0u;
    __syncthreads();
    int row = blockIdx.x;
    const float* d = &g_d2[(size_t)row * N_INST];
    for (int j = row + 1 + tid; j < N_INST; j += 256) {
        float dist = sqrtf(fmaxf(d[j], 0.f));
        int bin = (int)floorf((dist - 2.5f) * 2.0f) + 1;
        bin = max(0, min(127, bin));
        atomicAdd(&h[w][bin], 2u);
    }
    __syncthreads();
    for (int i = tid; i < 128; i += 256) {
        unsigned int s = 0;
        #pragma unroll
        for (int k = 0; k < 8; k++) s += h[k][i];
        if (s) atomicAdd(&g_hist[i], s);
    }
}

// ---------------- threshold select (mirrors the while_loop) ----------------
__global__ void select_thr_kernel() {
    if (threadIdx.x == 0 && blockIdx.x == 0) {
        float min_edges = 0.1f * (float)N_INST;
        unsigned int cum = 0;
        int k;
        for (k = 0; k < 127; k++) {
            cum += g_hist[k];
            if (!((float)cum < min_edges)) break;
        }
        float thr = 2.5f + 0.5f * (float)k;
        g_thr2[0] = thr * thr;
    }
}

// ---------------- degrees ----------------
__global__ __launch_bounds__(256) void deg_kernel() {
    int warp = (blockIdx.x * 256 + threadIdx.x) >> 5;
    int lane = threadIdx.x & 31;
    if (warp >= N_INST) return;
    float thr2 = g_thr2[0];
    const float* d = &g_d2[(size_t)warp * N_INST];
    int cnt = 0;
    for (int j = lane; j < N_INST; j += 32)
        if (d[j] < thr2 && j != warp) cnt++;
    #pragma unroll
    for (int o = 16; o > 0; o >>= 1) cnt += __shfl_xor_sync(0xffffffffu, cnt, o);
    if (!lane) {
        float dg = (float)cnt;
        g_degi[warp] = cnt;
        g_rs[warp]  = 1.f / fmaxf(dg, 1.f);
        g_rs1[warp] = 1.f / (dg + 1.f);
    }
}

// ---------------- CSR row pointer scan ----------------
__global__ __launch_bounds__(1024) void scan_kernel() {
    __shared__ int s[1024];
    int t = threadIdx.x;
    int c[4]; int sum = 0;
    #pragma unroll
    for (int i = 0; i < 4; i++) { c[i] = g_degi[t * 4 + i]; sum += c[i]; }
    s[t] = sum;
    __syncthreads();
    for (int off = 1; off < 1024; off <<= 1) {
        int v = (t >= off) ? s[t - off] : 0;
        __syncthreads();
        s[t] += v;
        __syncthreads();
    }
    int base = s[t] - sum;
    #pragma unroll
    for (int i = 0; i < 4; i++) { g_rowptr[t * 4 + i] = base; base += c[i]; }
    if (t == 1023) g_rowptr[N_INST] = base;
}

// ---------------- CSR index fill ----------------
__global__ __launch_bounds__(256) void fill_kernel() {
    int warp = (blockIdx.x * 256 + threadIdx.x) >> 5;
    int lane = threadIdx.x & 31;
    if (warp >= N_INST) return;
    float thr2 = g_thr2[0];
    const float* d = &g_d2[(size_t)warp * N_INST];
    int base = g_rowptr[warp];
    for (int j0 = 0; j0 < N_INST; j0 += 32) {
        int j = j0 + lane;
        bool p = (d[j] < thr2) && (j != warp);
        unsigned int m = __ballot_sync(0xffffffffu, p);
        if (p) {
            int pos = __popc(m & ((1u << lane) - 1u));
            g_idx[base + pos] = j;
        }
        base += __popc(m);
    }
}

// ---------------- sparse AH = A @ H ----------------
__global__ __launch_bounds__(128) void spmm_kernel() {
    int row = blockIdx.x;
    int f4 = threadIdx.x;
    if (f4 >= 125) return;
    int s = g_rowptr[row], e = g_rowptr[row + 1];
    float4 acc = make_float4(0.f, 0.f, 0.f, 0.f);
    const float4* H4 = (const float4*)g_H;
    for (int i = s; i < e; i++) {
        int j = g_idx[i];
        float4 v = H4[(size_t)j * 125 + f4];
        acc.x += v.x; acc.y += v.y; acc.z += v.z; acc.w += v.w;
    }
    ((float4*)g_AH)[(size_t)row * 125 + f4] = acc;
}

// ---------------- BN stats / finish ----------------
__global__ __launch_bounds__(512) void bnstats_kernel() {
    int f = threadIdx.x;
    if (f >= LF) return;
    int r0 = blockIdx.x * 128;
    float s = 0.f, q = 0.f;
    for (int r = 0; r < 128; r++) {
        float v = g_Zl[(size_t)(r0 + r) * LF + f];
        s += v; q += v * v;
    }
    atomicAdd(&g_bnsum[f], s);
    atomicAdd(&g_bnsq[f], q);
}
__global__ void bnfinish_kernel(const float* __restrict__ bng, const float* __restrict__ bnb) {
    int f = blockIdx.x * blockDim.x + threadIdx.x;
    if (f >= LF) return;
    float m = g_bnsum[f] * (1.f / (float)N_INST);
    float var = g_bnsq[f] * (1.f / (float)N_INST) - m * m;
    float a = bng[f] * rsqrtf(var + 1e-5f);
    g_bna[f] = a;
    g_bnbs[f] = bnb[f] - m * a;
}

// ---------------- soft assignment S ----------------
__global__ __launch_bounds__(256) void s_kernel(const float* __restrict__ wout,
    const float* __restrict__ bout, const float* __restrict__ wroot) {
    int warp = (blockIdx.x * 256 + threadIdx.x) >> 5;
    int lane = threadIdx.x & 31;
    if (warp >= N_INST) return;
    const float* ah = &g_AH[(size_t)warp * LF];
    const float* h  = &g_H[(size_t)warp * LF];
    float r1 = g_rs1[warp];
    float acc[CC] = {0.f, 0.f, 0.f, 0.f, 0.f};
    for (int k = lane; k < LF; k += 32) {
        float hv = h[k];
        float a = (ah[k] + hv) * r1;
        #pragma unroll
        for (int c = 0; c < CC; c++)
            acc[c] += a * wout[c * LF + k] + hv * wroot[c * LF + k];
    }
    #pragma unroll
    for (int c = 0; c < CC; c++)
        #pragma unroll
        for (int o = 16; o > 0; o >>= 1)
            acc[c] += __shfl_xor_sync(0xffffffffu, acc[c], o);
    if (!lane) {
        float t[CC], m = -1e30f;
        #pragma unroll
        for (int c = 0; c < CC; c++) { t[c] = acc[c] + bout[c]; m = fmaxf(m, t[c]); }
        float s = 0.f;
        #pragma unroll
        for (int c = 0; c < CC; c++) { t[c] = expf(t[c] - m); s += t[c]; }
        float inv = 1.f / s;
        #pragma unroll
        for (int c = 0; c < CC; c++) g_S[warp * CC + c] = t[c] * inv;
    }
}

// ---------------- AS = A @ S (CSR) ----------------
__global__ __launch_bounds__(256) void as_kernel() {
    int warp = (blockIdx.x * 256 + threadIdx.x) >> 5;
    int lane = threadIdx.x & 31;
    if (warp >= N_INST) return;
    int s = g_rowptr[warp], e = g_rowptr[warp + 1];
    float acc[CC] = {0.f, 0.f, 0.f, 0.f, 0.f};
    for (int i = s + lane; i < e; i += 32) {
        int j = g_idx[i];
        const float* sp = &g_S[j * CC];
        #pragma unroll
        for (int c = 0; c < CC; c++) acc[c] += sp[c];
    }
    #pragma unroll
    for (int c = 0; c < CC; c++)
        #pragma unroll
        for (int o = 16; o > 0; o >>= 1)
            acc[c] += __shfl_xor_sync(0xffffffffu, acc[c], o);
    if (!lane)
        #pragma unroll
        for (int c = 0; c < CC; c++) g_AS[warp * CC + c] = acc[c];
}

// ---------------- coar = S^T @ Z with BN folded ----------------
__global__ __launch_bounds__(128) void coar_kernel() {
    __shared__ float ss[256 * CC];
    int f = blockIdx.x * 128 + threadIdx.x;
    float acc[CC] = {0.f, 0.f, 0.f, 0.f, 0.f};
    float ssum[CC] = {0.f, 0.f, 0.f, 0.f, 0.f};
    for (int r0 = 0; r0 < N_INST; r0 += 256) {
        for (int i = threadIdx.x; i < 256 * CC; i += 128) ss[i] = g_S[r0 * CC + i];
        __syncthreads();
        if (f < LF) {
            for (int r = 0; r < 256; r++) {
                float z = g_Zl[(size_t)(r0 + r) * LF + f];
                #pragma unroll
                for (int c = 0; c < CC; c++) {
                    acc[c] += ss[r * CC + c] * z;
                    ssum[c] += ss[r * CC + c];
                }
            }
        }
        __syncthreads();
    }
    if (f < LF) {
        float a = g_bna[f], b = g_bnbs[f];
        #pragma unroll
        for (int c = 0; c < CC; c++) g_coar[c * LF + f] = a * acc[c] + b * ssum[c];
    }
}

// ---------------- Ac = S^T @ AS ----------------
__global__ __launch_bounds__(256) void ac_kernel() {
    __shared__ float sAc[CC * CC];
    int tid = threadIdx.x;
    if (tid < CC * CC) sAc[tid] = 0.f;
    __syncthreads();
    float acc[CC * CC];
    #pragma unroll
    for (int i = 0; i < CC * CC; i++) acc[i] = 0.f;
    for (int r = tid; r < N_INST; r += 256) {
        float sv[CC], av[CC];
        #pragma unroll
        for (int c = 0; c < CC; c++) { sv[c] = g_S[r * CC + c]; av[c] = g_AS[r * CC + c]; }
        #pragma unroll
        for (int c1 = 0; c1 < CC; c1++)
            #pragma unroll
            for (int c2 = 0; c2 < CC; c2++)
                acc[c1 * CC + c2] += sv[c1] * av[c2];
    }
    #pragma unroll
    for (int i = 0; i < CC * CC; i++) atomicAdd(&sAc[i], acc[i]);
    __syncthreads();
    if (tid < CC * CC) g_Ac[tid] = sAc[tid];
}

// ---------------- Mc / coarse degrees ----------------
__global__ void mc_kernel() {
    if (threadIdx.x == 0 && blockIdx.x == 0) {
        float s = 0.f;
        for (int i = 0; i < CC * CC; i++) s += g_Ac[i];
        float mean = s * (1.f / (float)(CC * CC));
        for (int c = 0; c < CC; c++) {
            float dg = 0.f;
            for (int j = 0; j < CC; j++) {
                float a = g_Ac[c * CC + j];
                float m = (a >= mean && a > 0.f) ? 1.f : 0.f;
                g_Mc[c * CC + j] = m;
                dg += m;
            }
            g_invdegc[c] = 1.f / fmaxf(dg, 1.f);
        }
    }
}

// ---------------- neigh = (Mc @ coar)/deg ----------------
__global__ void neigh_kernel() {
    int f = blockIdx.x * blockDim.x + threadIdx.x;
    if (f >= LF) return;
    #pragma unroll
    for (int c = 0; c < CC; c++) {
        float s = 0.f;
        #pragma unroll
        for (int j = 0; j < CC; j++) s += g_Mc[c * CC + j] * g_coar[j * LF + f];
        g_neigh[c * LF + f] = s * g_invdegc[c];
    }
}

// ---------------- coarse SAGE + leaky ----------------
__global__ __launch_bounds__(256) void csage_kernel(const float* __restrict__ wl,
    const float* __restrict__ bl, const float* __restrict__ wr) {
    int idx = blockIdx.x * 256 + threadIdx.x;
    if (idx >= CC * LF) return;
    int c = idx / LF, f = idx % LF;
    float acc = bl[f];
    const float* ng = &g_neigh[c * LF];
    const float* cr = &g_coar[c * LF];
    const float* wlr = &wl[f * LF];
    const float* wrr = &wr[f * LF];
    for (int k = 0; k < LF; k++)
        acc += ng[k] * wlr[k] + cr[k] * wrr[k];
    g_E[idx] = acc > 0.f ? acc : 0.01f * acc;
}

// ---------------- coarse BN + neighbor max-pool ----------------
__global__ __launch_bounds__(512) void cbnpool_kernel(const float* __restrict__ bng,
                                                      const float* __restrict__ bnb) {
    int f = threadIdx.x;
    if (f >= LF) return;
    float v[CC], s = 0.f;
    #pragma unroll
    for (int c = 0; c < CC; c++) { v[c] = g_E[c * LF + f]; s += v[c]; }
    float m = s * (1.f / (float)CC);
    float var = 0.f;
    #pragma unroll
    for (int c = 0; c < CC; c++) { float d = v[c] - m; var += d * d; }
    var *= (1.f / (float)CC);
    float a = bng[f] * rsqrtf(var + 1e-5f);
    float z[CC];
    #pragma unroll
    for (int c = 0; c < CC; c++) z[c] = (v[c] - m) * a + bnb[f];
    #pragma unroll
    for (int c = 0; c < CC; c++) {
        float p = -1e30f;
        #pragma unroll
        for (int j = 0; j < CC; j++) {
            bool mk = (c == j) || (g_Mc[c * CC + j] > 0.f);
            if (mk) p = fmaxf(p, z[j]);
        }
        g_pooled[c * LF + f] = p;
    }
}

// ---------------- MLP head + softmax + output ----------------
__global__ __launch_bounds__(256) void mlp_kernel(const float* __restrict__ w1,
    const float* __restrict__ b1, const float* __restrict__ w2,
    const float* __restrict__ b2, float* __restrict__ out, int out_size) {
    __shared__ float h1[CC * 250];
    __shared__ float lg[CC];
    int tid = threadIdx.x;
    for (int idx = tid; idx < CC * 250; idx += 256) {
        int c = idx / 250, j = idx % 250;
        float acc = b1[j];
        const float* p = &g_pooled[c * LF];
        const float* wr = &w1[j * LF];
        for (int k = 0; k < LF; k++) acc += p[k] * wr[k];
        h1[idx] = acc > 0.f ? acc : 0.01f * acc;
    }
    __syncthreads();
    if (tid < CC) {
        float acc = b2[0];
        for (int j = 0; j < 250; j++) acc += h1[tid * 250 + j] * w2[j];
        lg[tid] = acc > 0.f ? acc : 0.01f * acc;
    }
    __syncthreads();
    if (tid == 0) {
        float m = -1e30f;
        for (int c = 0; c < CC; c++) m = fmaxf(m, lg[c]);
        float s = 0.f, e[CC];
        for (int c = 0; c < CC; c++) { e[c] = expf(lg[c] - m); s += e[c]; }
        float p = 0.f;
        for (int c = 0; c < CC; c++) p = fmaxf(p, e[c] / s);
        out[0] = p;
        if (out_size > 1) out[1] = (p >= 0.5f) ? 1.f : 0.f;
    }
}

// ---------------- host ----------------
extern "C" void kernel_launch(void* const* d_in, const int* in_sizes, int n_in,
                              void* d_out, int out_size) {
    const float* x       = (const float*)d_in[0];
    const float* conv1_w = (const float*)d_in[1];
    const float* conv1_b = (const float*)d_in[2];
    const float* conv2_w = (const float*)d_in[3];
    const float* conv2_b = (const float*)d_in[4];
    const float* fc_w    = (const float*)d_in[5];
    const float* fc_b    = (const float*)d_in[6];
    const float* sage_wl = (const float*)d_in[7];
    const float* sage_bl = (const float*)d_in[8];
    const float* sage_wr = (const float*)d_in[9];
    const float* bn_g    = (const float*)d_in[10];
    const float* bn_b    = (const float*)d_in[11];
    const float* cg_wout = (const float*)d_in[12];
    const float* cg_bout = (const float*)d_in[13];
    const float* cg_wroot= (const float*)d_in[14];
    const float* lin1_w  = (const float*)d_in[15];
    const float* lin1_b  = (const float*)d_in[16];
    const float* lin2_w  = (const float*)d_in[17];
    const float* lin2_b  = (const float*)d_in[18];
    float* out = (float*)d_out;

    float *pP2, *pH, *pAH, *pZl, *pRS;
    cudaGetSymbolAddress((void**)&pP2, g_P2);
    cudaGetSymbolAddress((void**)&pH,  g_H);
    cudaGetSymbolAddress((void**)&pAH, g_AH);
    cudaGetSymbolAddress((void**)&pZl, g_Zl);
    cudaGetSymbolAddress((void**)&pRS, g_rs);

    cudaFuncSetAttribute(gram_mma_kernel,
                         cudaFuncAttributeMaxDynamicSharedMemorySize, GRAM_SMEM);
    cudaFuncSetAttribute(conv2_mma_kernel,
                         cudaFuncAttributeMaxDynamicSharedMemorySize, C2_SMEM);
    cudaFuncSetAttribute(gemm_mma<true, true, true, 2>,
                         cudaFuncAttributeMaxDynamicSharedMemorySize, GRAM_SMEM);

    init_kernel<<<1, 512>>>();
    conv1_kernel<<<N_INST, 512>>>(x, conv1_w, conv1_b);

    // conv2 via implicit GEMM 3xTF32 mma (scratch = g_d2), then bias+relu+maxpool
    conv2_mma_kernel<<<2048, 256, C2_SMEM>>>(conv2_w);
    pool2_kernel<<<N_INST, 256>>>(conv2_b);

    // FC: H = relu(P2 @ fc_w^T + fc_b)  (FFMA sgemm — faster at this grid size)
    sgemm_tb<false, false, true, 1>
        <<<dim3(4, 32), 256>>>(pP2, fc_w, pH, N_INST, LF, 800, 800, 800, LF,
                               fc_b, nullptr);

    split_kernel<<<(N_INST * (KPAD/4) + 255) / 256, 256>>>();
    sq_kernel<<<512, 256>>>();

    // d2 via 3xTF32 mma.sync Gram (symmetric, mirrored)
    gram_mma_kernel<<<dim3(32, 32), 256, GRAM_SMEM>>>();

    hist_kernel<<<N_INST, 256>>>();
    select_thr_kernel<<<1, 32>>>();
    deg_kernel<<<512, 256>>>();
    scan_kernel<<<1, 1024>>>();
    fill_kernel<<<512, 256>>>();
    spmm_kernel<<<N_INST, 128>>>();

    // Fused SAGE: Zl = leaky((rs*AH) @ wl^T + bl + H @ wr^T) via dual 3xTF32 mma
    gemm_mma<true, true, true, 2>
        <<<dim3(4, 32), 256, GRAM_SMEM>>>(pAH, sage_wl, pH, sage_wr, pZl,
                                          N_INST, LF, LF, LF, LF, LF,
                                          sage_bl, pRS);

    bnstats_kernel<<<32, 512>>>();
    bnfinish_kernel<<<1, 512>>>(bn_g, bn_b);

    s_kernel<<<512, 256>>>(cg_wout, cg_bout, cg_wroot);
    as_kernel<<<512, 256>>>();
    coar_kernel<<<4, 128>>>();
    ac_kernel<<<1, 256>>>();
    mc_kernel<<<1, 32>>>();
    neigh_kernel<<<1, 512>>>();
    csage_kernel<<<10, 256>>>(sage_wl, sage_bl, sage_wr);
    cbnpool_kernel<<<1, 512>>>(bn_g, bn_b);
    mlp_kernel<<<1, 256>>>(lin1_w, lin1_b, lin2_w, lin2_b, out, out_size);
}

// round 9
// speedup vs baseline: 1.1712x; 1.1712x over previous
#include <cuda_runtime.h>
#include <math.h>
#include <stdint.h>

#define N_INST 4096
#define LF 500
#define KPAD 512
#define CC 5

// ---------------- scratch (device globals; no allocation) ----------------
__device__ __align__(128) float g_P1[N_INST*2880];
__device__ __align__(128) float g_P2[N_INST*800];
__device__ __align__(128) float g_H [N_INST*LF];
__device__ __align__(128) float g_Hhi[N_INST*KPAD];
__device__ __align__(128) float g_Hlo[N_INST*KPAD];
__device__ __align__(128) float g_d2[(size_t)N_INST*N_INST];
__device__ __align__(128) float g_AH[N_INST*LF];
__device__ __align__(128) float g_Zl[N_INST*LF];
// pre-split operand buffers
__device__ __align__(128) float g_P2hi[N_INST*800], g_P2lo[N_INST*800];
__device__ __align__(128) float g_fwhi[512*800],   g_fwlo[512*800];
__device__ __align__(128) float g_Xhi[N_INST*KPAD], g_Xlo[N_INST*KPAD];
__device__ __align__(128) float g_wlhi[512*512],   g_wllo[512*512];
__device__ __align__(128) float g_wrhi[512*512],   g_wrlo[512*512];
__device__ float g_S [N_INST*CC];
__device__ float g_AS[N_INST*CC];
__device__ float g_sq[N_INST];
__device__ float g_rs[N_INST];    // 1/max(deg,1)
__device__ float g_rs1[N_INST];   // 1/(deg+1)
__device__ int   g_degi[N_INST];
__device__ int   g_rowptr[N_INST+1];
__device__ int   g_idx[(size_t)N_INST*N_INST];
__device__ unsigned int g_hist[128];
__device__ float g_thr2[1];
__device__ float g_bnsum[LF], g_bnsq[LF], g_bna[LF], g_bnbs[LF];
__device__ float g_coar[CC*LF], g_neigh[CC*LF], g_E[CC*LF], g_pooled[CC*LF];
__device__ float g_Ac[CC*CC], g_Mc[CC*CC], g_invdegc[CC];

// ---------------- init ----------------
__global__ void init_kernel() {
    int t = threadIdx.x;
    for (int i = t; i < 128; i += 512) g_hist[i] = 0u;
    for (int i = t; i < LF; i += 512) { g_bnsum[i] = 0.f; g_bnsq[i] = 0.f; }
}

// ---------------- conv1 + relu + maxpool: [N,1,28,28] -> [N,20,12,12] ----------------
__global__ __launch_bounds__(512) void conv1_kernel(const float* __restrict__ x,
    const float* __restrict__ w, const float* __restrict__ b) {
    __shared__ float simg[784];
    __shared__ float sw[500];
    __shared__ float sb[20];
    int n = blockIdx.x;
    int tid = threadIdx.x;
    const float* img = x + n * 784;
    for (int i = tid; i < 784; i += 512) simg[i] = img[i];
    for (int i = tid; i < 500; i += 512) sw[i] = w[i];
    if (tid < 20) sb[tid] = b[tid];
    __syncthreads();
    if (tid < 480) {
        int ch = tid / 24;
        int rem = tid % 24;
        int py = rem / 2;
        int half = rem % 2;
        int cx0 = half * 12;
        float acc0[12], acc1[12];
        #pragma unroll
        for (int xx = 0; xx < 12; xx++) { acc0[xx] = 0.f; acc1[xx] = 0.f; }
        const float* wch = &sw[ch * 25];
        int ry0 = 2 * py;
        for (int ki = 0; ki < 5; ki++) {
            float in0[16], in1[16];
            const float* r0 = &simg[(ry0 + ki) * 28 + cx0];
            const float* r1 = &simg[(ry0 + ki + 1) * 28 + cx0];
            #pragma unroll
            for (int t2 = 0; t2 < 16; t2++) { in0[t2] = r0[t2]; in1[t2] = r1[t2]; }
            #pragma unroll
            for (int kj = 0; kj < 5; kj++) {
                float wv = wch[ki * 5 + kj];
                #pragma unroll
                for (int xx = 0; xx < 12; xx++) {
                    acc0[xx] += in0[xx + kj] * wv;
                    acc1[xx] += in1[xx + kj] * wv;
                }
            }
        }
        float bv = sb[ch];
        float* outp = &g_P1[n * 2880 + ch * 144 + py * 12 + half * 6];
        #pragma unroll
        for (int px = 0; px < 6; px++) {
            float m = fmaxf(fmaxf(acc0[2*px], acc0[2*px+1]), fmaxf(acc1[2*px], acc1[2*px+1]));
            outp[px] = fmaxf(m + bv, 0.f);
        }
    }
}

// ---------------- conv2 + relu + maxpool: [N,20,12,12] -> [N,50,4,4] ----------------
__global__ __launch_bounds__(256) void conv2_kernel(const float* __restrict__ w,
                                                    const float* __restrict__ b) {
    __shared__ float sin[2880];
    int n = blockIdx.x;
    int tid = threadIdx.x;
    const float* src = &g_P1[n * 2880];
    for (int i = tid; i < 2880; i += 256) sin[i] = src[i];
    __syncthreads();
    if (tid < 200) {
        int oc = tid / 4, py = tid % 4;
        float acc0[8], acc1[8];
        #pragma unroll
        for (int xx = 0; xx < 8; xx++) { acc0[xx] = 0.f; acc1[xx] = 0.f; }
        const float* wb = w + oc * 500;
        int ry0 = 2 * py;
        for (int ic = 0; ic < 20; ic++) {
            const float* chin = &sin[ic * 144];
            #pragma unroll
            for (int ki = 0; ki < 5; ki++) {
                float in0[12], in1[12];
                const float* r0 = &chin[(ry0 + ki) * 12];
                const float* r1 = &chin[(ry0 + ki + 1) * 12];
                #pragma unroll
                for (int t2 = 0; t2 < 12; t2++) { in0[t2] = r0[t2]; in1[t2] = r1[t2]; }
                #pragma unroll
                for (int kj = 0; kj < 5; kj++) {
                    float wv = __ldg(&wb[ic * 25 + ki * 5 + kj]);
                    #pragma unroll
                    for (int xx = 0; xx < 8; xx++) {
                        acc0[xx] += in0[xx + kj] * wv;
                        acc1[xx] += in1[xx + kj] * wv;
                    }
                }
            }
        }
        float bv = b[oc];
        float* outp = &g_P2[n * 800 + oc * 16 + py * 4];
        #pragma unroll
        for (int px = 0; px < 4; px++) {
            float m = fmaxf(fmaxf(acc0[2*px], acc0[2*px+1]), fmaxf(acc1[2*px], acc1[2*px+1]));
            outp[px] = fmaxf(m + bv, 0.f);
        }
    }
}

// ---------------- shared mma helpers ----------------
#define GSTRIDE 36
#define GRAM_SMEM (4 * 128 * GSTRIDE * 4)     // 73728 B

__device__ __forceinline__ void mma_tf32(float* c, const uint32_t* a, uint32_t b0, uint32_t b1) {
    asm volatile(
        "mma.sync.aligned.m16n8k8.row.col.f32.tf32.tf32.f32 "
        "{%0,%1,%2,%3}, {%4,%5,%6,%7}, {%8,%9}, {%0,%1,%2,%3};\n"
        : "+f"(c[0]), "+f"(c[1]), "+f"(c[2]), "+f"(c[3])
        : "r"(a[0]), "r"(a[1]), "r"(a[2]), "r"(a[3]), "r"(b0), "r"(b1));
}

__device__ __forceinline__ void tf32_split(float v, float& hi, float& lo) {
    uint32_t h = __float_as_uint(v) & 0xFFFFE000u;
    float hf = __uint_as_float(h);
    float lf = v - hf;
    uint32_t l;
    asm("cvt.rna.tf32.f32 %0, %1;" : "=r"(l) : "f"(lf));
    hi = hf;
    lo = __uint_as_float(l);
}

// ---------------- generic split: src[srcRows,srcCols] (ld) -> hi/lo [dstRows,kpad] ----------------
__global__ __launch_bounds__(256) void splitg_kernel(
    const float* __restrict__ src, float* __restrict__ hi, float* __restrict__ lo,
    int dstRows, int srcRows, int srcCols, int ld, int kpad,
    const float* __restrict__ rowscale) {
    int idx = blockIdx.x * 256 + threadIdx.x;
    if (idx >= dstRows * kpad) return;
    int r = idx / kpad;
    int c = idx - r * kpad;
    float v = 0.f;
    if (r < srcRows && c < srcCols) {
        v = src[(size_t)r * ld + c];
        if (rowscale) v *= rowscale[r];
    }
    float h, l;
    tf32_split(v, h, l);
    hi[idx] = h;
    lo[idx] = l;
}

// ---------------- pre-split 3xTF32 mma GEMM: C = A1@B1^T (+ A2@B2^T) ----------------
// All operands pre-split hi/lo, padded row stride = kpad (mult of 32). bias + ACT.
template<bool DUAL, int ACT>
__global__ __launch_bounds__(256) void gemm_ps(
    const float* __restrict__ A1hi, const float* __restrict__ A1lo,
    const float* __restrict__ B1hi, const float* __restrict__ B1lo,
    const float* __restrict__ A2hi, const float* __restrict__ A2lo,
    const float* __restrict__ B2hi, const float* __restrict__ B2lo,
    float* __restrict__ C, int M, int Nreal, int kpad, int ldc,
    const float* __restrict__ bias) {
    extern __shared__ float smem[];
    float* sAhi = smem;
    float* sAlo = smem + 128 * GSTRIDE;
    float* sBhi = smem + 2 * 128 * GSTRIDE;
    float* sBlo = smem + 3 * 128 * GSTRIDE;

    int m0 = blockIdx.y * 128, n0 = blockIdx.x * 128;
    int tid = threadIdx.x;
    int lane = tid & 31, wid = tid >> 5;
    int warp_m = wid & 3, warp_n = wid >> 2;
    int group = lane >> 2, tid4 = lane & 3;

    float acc[2][8][4];
    #pragma unroll
    for (int mt = 0; mt < 2; mt++)
        #pragma unroll
        for (int nt = 0; nt < 8; nt++)
            #pragma unroll
            for (int q = 0; q < 4; q++) acc[mt][nt][q] = 0.f;

    int nkc = kpad >> 5;
    int npair = DUAL ? 2 : 1;
    for (int p = 0; p < npair; p++) {
        const float* gAhi = ((DUAL && p) ? A2hi : A1hi) + (size_t)m0 * kpad;
        const float* gAlo = ((DUAL && p) ? A2lo : A1lo) + (size_t)m0 * kpad;
        const float* gBhi = ((DUAL && p) ? B2hi : B1hi) + (size_t)n0 * kpad;
        const float* gBlo = ((DUAL && p) ? B2lo : B1lo) + (size_t)n0 * kpad;
        for (int kc = 0; kc < nkc; kc++) {
            #pragma unroll
            for (int t = 0; t < 4; t++) {
                int id = tid + 256 * t;          // 0..1023
                int row = id >> 3, c4 = id & 7;
                size_t goff = (size_t)row * kpad + kc * 32 + c4 * 4;
                int soff = row * GSTRIDE + c4 * 4;
                *(float4*)(sAhi + soff) = *(const float4*)(gAhi + goff);
                *(float4*)(sAlo + soff) = *(const float4*)(gAlo + goff);
                *(float4*)(sBhi + soff) = *(const float4*)(gBhi + goff);
                *(float4*)(sBlo + soff) = *(const float4*)(gBlo + goff);
            }
            __syncthreads();
            #pragma unroll
            for (int ks = 0; ks < 4; ks++) {
                int k0 = ks * 8;
                uint32_t ahi[2][4], alo[2][4];
                #pragma unroll
                for (int mt = 0; mt < 2; mt++) {
                    int r0 = (warp_m * 32 + mt * 16 + group) * GSTRIDE;
                    int r8 = r0 + 8 * GSTRIDE;
                    ahi[mt][0] = __float_as_uint(sAhi[r0 + k0 + tid4]);
                    ahi[mt][1] = __float_as_uint(sAhi[r8 + k0 + tid4]);
                    ahi[mt][2] = __float_as_uint(sAhi[r0 + k0 + tid4 + 4]);
                    ahi[mt][3] = __float_as_uint(sAhi[r8 + k0 + tid4 + 4]);
                    alo[mt][0] = __float_as_uint(sAlo[r0 + k0 + tid4]);
                    alo[mt][1] = __float_as_uint(sAlo[r8 + k0 + tid4]);
                    alo[mt][2] = __float_as_uint(sAlo[r0 + k0 + tid4 + 4]);
                    alo[mt][3] = __float_as_uint(sAlo[r8 + k0 + tid4 + 4]);
                }
                #pragma unroll
                for (int nt = 0; nt < 8; nt++) {
                    int nb = (warp_n * 64 + nt * 8 + group) * GSTRIDE;
                    uint32_t bhi0 = __float_as_uint(sBhi[nb + k0 + tid4]);
                    uint32_t bhi1 = __float_as_uint(sBhi[nb + k0 + tid4 + 4]);
                    uint32_t blo0 = __float_as_uint(sBlo[nb + k0 + tid4]);
                    uint32_t blo1 = __float_as_uint(sBlo[nb + k0 + tid4 + 4]);
                    #pragma unroll
                    for (int mt = 0; mt < 2; mt++) {
                        mma_tf32(acc[mt][nt], ahi[mt], bhi0, bhi1);
                        mma_tf32(acc[mt][nt], ahi[mt], blo0, blo1);
                        mma_tf32(acc[mt][nt], alo[mt], bhi0, bhi1);
                    }
                }
            }
            __syncthreads();
        }
    }

    #pragma unroll
    for (int mt = 0; mt < 2; mt++) {
        int gm0 = m0 + warp_m * 32 + mt * 16 + group;
        int gm8 = gm0 + 8;
        #pragma unroll
        for (int nt = 0; nt < 8; nt++) {
            int gn = n0 + warp_n * 64 + nt * 8 + 2 * tid4;
            #pragma unroll
            for (int q = 0; q < 2; q++) {
                int gnn = gn + q;
                if (gnn >= Nreal) continue;
                float bv = bias[gnn];
                if (gm0 < M) {
                    float v = acc[mt][nt][q] + bv;
                    if (ACT == 1) v = fmaxf(v, 0.f);
                    else if (ACT == 2) v = v > 0.f ? v : 0.01f * v;
                    C[(size_t)gm0 * ldc + gnn] = v;
                }
                if (gm8 < M) {
                    float v = acc[mt][nt][2 + q] + bv;
                    if (ACT == 1) v = fmaxf(v, 0.f);
                    else if (ACT == 2) v = v > 0.f ? v : 0.01f * v;
                    C[(size_t)gm8 * ldc + gnn] = v;
                }
            }
        }
    }
}

// ---------------- split H into tf32 hi/lo, padded to KPAD (for gram + SAGE pair2) ----------------
__global__ __launch_bounds__(256) void split_kernel() {
    int idx = blockIdx.x * 256 + threadIdx.x;      // float4 index
    if (idx >= N_INST * (KPAD / 4)) return;
    int row = idx >> 7;
    int c4  = idx & 127;
    float4 hi, lo;
    if (c4 < 125) {
        float4 v = *(const float4*)(g_H + (size_t)row * LF + c4 * 4);
        tf32_split(v.x, hi.x, lo.x);
        tf32_split(v.y, hi.y, lo.y);
        tf32_split(v.z, hi.z, lo.z);
        tf32_split(v.w, hi.w, lo.w);
    } else {
        hi = make_float4(0.f, 0.f, 0.f, 0.f);
        lo = hi;
    }
    ((float4*)g_Hhi)[idx] = hi;
    ((float4*)g_Hlo)[idx] = lo;
}

// ---------------- row squared norms ----------------
__global__ __launch_bounds__(256) void sq_kernel() {
    int warp = (blockIdx.x * 256 + threadIdx.x) >> 5;
    int lane = threadIdx.x & 31;
    if (warp >= N_INST) return;
    const float* h = &g_H[warp * LF];
    float s = 0.f;
    for (int k = lane; k < LF; k += 32) { float v = h[k]; s += v * v; }
    #pragma unroll
    for (int o = 16; o > 0; o >>= 1) s += __shfl_xor_sync(0xffffffffu, s, o);
    if (!lane) g_sq[warp] = s;
}

// ---------------- 3xTF32 mma.sync Gram: d2 = sq_i + sq_j - 2*H H^T ----------------
__global__ __launch_bounds__(256) void gram_mma_kernel() {
    extern __shared__ float smem[];
    int m0 = blockIdx.y * 128, n0 = blockIdx.x * 128;
    if (m0 > n0) return;
    float* sAhi = smem;
    float* sAlo = smem + 128 * GSTRIDE;
    float* sBhi = smem + 2 * 128 * GSTRIDE;
    float* sBlo = smem + 3 * 128 * GSTRIDE;

    int tid = threadIdx.x;
    int lane = tid & 31, wid = tid >> 5;
    int warp_m = wid & 3, warp_n = wid >> 2;
    int group = lane >> 2, tid4 = lane & 3;

    float acc[2][8][4];
    #pragma unroll
    for (int mt = 0; mt < 2; mt++)
        #pragma unroll
        for (int nt = 0; nt < 8; nt++)
            #pragma unroll
            for (int q = 0; q < 4; q++) acc[mt][nt][q] = 0.f;

    const float* gAhi = g_Hhi + (size_t)m0 * KPAD;
    const float* gAlo = g_Hlo + (size_t)m0 * KPAD;
    const float* gBhi = g_Hhi + (size_t)n0 * KPAD;
    const float* gBlo = g_Hlo + (size_t)n0 * KPAD;

    for (int kc = 0; kc < KPAD / 32; kc++) {
        #pragma unroll
        for (int t = 0; t < 4; t++) {
            int id = tid + 256 * t;
            int row = id >> 3, c4 = id & 7;
            size_t goff = (size_t)row * KPAD + kc * 32 + c4 * 4;
            int soff = row * GSTRIDE + c4 * 4;
            *(float4*)(sAhi + soff) = *(const float4*)(gAhi + goff);
            *(float4*)(sAlo + soff) = *(const float4*)(gAlo + goff);
            *(float4*)(sBhi + soff) = *(const float4*)(gBhi + goff);
            *(float4*)(sBlo + soff) = *(const float4*)(gBlo + goff);
        }
        __syncthreads();
        #pragma unroll
        for (int ks = 0; ks < 4; ks++) {
            int k0 = ks * 8;
            uint32_t ahi[2][4], alo[2][4];
            #pragma unroll
            for (int mt = 0; mt < 2; mt++) {
                int r0 = (warp_m * 32 + mt * 16 + group) * GSTRIDE;
                int r8 = r0 + 8 * GSTRIDE;
                ahi[mt][0] = __float_as_uint(sAhi[r0 + k0 + tid4]);
                ahi[mt][1] = __float_as_uint(sAhi[r8 + k0 + tid4]);
                ahi[mt][2] = __float_as_uint(sAhi[r0 + k0 + tid4 + 4]);
                ahi[mt][3] = __float_as_uint(sAhi[r8 + k0 + tid4 + 4]);
                alo[mt][0] = __float_as_uint(sAlo[r0 + k0 + tid4]);
                alo[mt][1] = __float_as_uint(sAlo[r8 + k0 + tid4]);
                alo[mt][2] = __float_as_uint(sAlo[r0 + k0 + tid4 + 4]);
                alo[mt][3] = __float_as_uint(sAlo[r8 + k0 + tid4 + 4]);
            }
            #pragma unroll
            for (int nt = 0; nt < 8; nt++) {
                int nb = (warp_n * 64 + nt * 8 + group) * GSTRIDE;
                uint32_t bhi0 = __float_as_uint(sBhi[nb + k0 + tid4]);
                uint32_t bhi1 = __float_as_uint(sBhi[nb + k0 + tid4 + 4]);
                uint32_t blo0 = __float_as_uint(sBlo[nb + k0 + tid4]);
                uint32_t blo1 = __float_as_uint(sBlo[nb + k0 + tid4 + 4]);
                #pragma unroll
                for (int mt = 0; mt < 2; mt++) {
                    mma_tf32(acc[mt][nt], ahi[mt], bhi0, bhi1);
                    mma_tf32(acc[mt][nt], ahi[mt], blo0, blo1);
                    mma_tf32(acc[mt][nt], alo[mt], bhi0, bhi1);
                }
            }
        }
        __syncthreads();
    }

    float* trans = smem;   // [128 n][stride 129 m]
    #pragma unroll
    for (int mt = 0; mt < 2; mt++) {
        int lm0 = warp_m * 32 + mt * 16 + group;
        int lm8 = lm0 + 8;
        float sq0 = g_sq[m0 + lm0], sq8 = g_sq[m0 + lm8];
        #pragma unroll
        for (int nt = 0; nt < 8; nt++) {
            int ln = warp_n * 64 + nt * 8 + 2 * tid4;
            float sqa = g_sq[n0 + ln], sqb = g_sq[n0 + ln + 1];
            float v00 = sq0 + sqa - 2.f * acc[mt][nt][0];
            float v01 = sq0 + sqb - 2.f * acc[mt][nt][1];
            float v80 = sq8 + sqa - 2.f * acc[mt][nt][2];
            float v81 = sq8 + sqb - 2.f * acc[mt][nt][3];
            *(float2*)&g_d2[(size_t)(m0 + lm0) * N_INST + n0 + ln] = make_float2(v00, v01);
            *(float2*)&g_d2[(size_t)(m0 + lm8) * N_INST + n0 + ln] = make_float2(v80, v81);
            trans[ln * 129 + lm0] = v00;
            trans[(ln + 1) * 129 + lm0] = v01;
            trans[ln * 129 + lm8] = v80;
            trans[(ln + 1) * 129 + lm8] = v81;
        }
    }
    __syncthreads();
    #pragma unroll
    for (int t = 0; t < 4; t++) {
        int id = tid + 256 * t;
        int n = id >> 3, c4 = id & 7;
        #pragma unroll
        for (int rep = 0; rep < 4; rep++) {
            int cc4 = c4 + rep * 8;
            float4 v;
            v.x = trans[n * 129 + cc4 * 4 + 0];
            v.y = trans[n * 129 + cc4 * 4 + 1];
            v.z = trans[n * 129 + cc4 * 4 + 2];
            v.w = trans[n * 129 + cc4 * 4 + 3];
            *(float4*)&g_d2[(size_t)(n0 + n) * N_INST + m0 + cc4 * 4] = v;
        }
    }
}

// ---------------- distance histogram (upper triangle x2, per-warp smem) ----------------
__global__ __launch_bounds__(256) void hist_kernel() {
    __shared__ unsigned int h[8][128];
    int tid = threadIdx.x, w = tid >> 5;
    for (int i = tid; i < 1024; i += 256) ((unsigned int*)h)[i] = 0u;
    __syncthreads();
    int row = blockIdx.x;
    const float* d = &g_d2[(size_t)row * N_INST];
    for (int j = row + 1 + tid; j < N_INST; j += 256) {
        float dist = sqrtf(fmaxf(d[j], 0.f));
        int bin = (int)floorf((dist - 2.5f) * 2.0f) + 1;
        bin = max(0, min(127, bin));
        atomicAdd(&h[w][bin], 2u);
    }
    __syncthreads();
    for (int i = tid; i < 128; i += 256) {
        unsigned int s = 0;
        #pragma unroll
        for (int k = 0; k < 8; k++) s += h[k][i];
        if (s) atomicAdd(&g_hist[i], s);
    }
}

// ---------------- threshold select ----------------
__global__ void select_thr_kernel() {
    if (threadIdx.x == 0 && blockIdx.x == 0) {
        float min_edges = 0.1f * (float)N_INST;
        unsigned int cum = 0;
        int k;
        for (k = 0; k < 127; k++) {
            cum += g_hist[k];
            if (!((float)cum < min_edges)) break;
        }
        float thr = 2.5f + 0.5f * (float)k;
        g_thr2[0] = thr * thr;
    }
}

// ---------------- degrees ----------------
__global__ __launch_bounds__(256) void deg_kernel() {
    int warp = (blockIdx.x * 256 + threadIdx.x) >> 5;
    int lane = threadIdx.x & 31;
    if (warp >= N_INST) return;
    float thr2 = g_thr2[0];
    const float* d = &g_d2[(size_t)warp * N_INST];
    int cnt = 0;
    for (int j = lane; j < N_INST; j += 32)
        if (d[j] < thr2 && j != warp) cnt++;
    #pragma unroll
    for (int o = 16; o > 0; o >>= 1) cnt += __shfl_xor_sync(0xffffffffu, cnt, o);
    if (!lane) {
        float dg = (float)cnt;
        g_degi[warp] = cnt;
        g_rs[warp]  = 1.f / fmaxf(dg, 1.f);
        g_rs1[warp] = 1.f / (dg + 1.f);
    }
}

// ---------------- CSR row pointer scan ----------------
__global__ __launch_bounds__(1024) void scan_kernel() {
    __shared__ int s[1024];
    int t = threadIdx.x;
    int c[4]; int sum = 0;
    #pragma unroll
    for (int i = 0; i < 4; i++) { c[i] = g_degi[t * 4 + i]; sum += c[i]; }
    s[t] = sum;
    __syncthreads();
    for (int off = 1; off < 1024; off <<= 1) {
        int v = (t >= off) ? s[t - off] : 0;
        __syncthreads();
        s[t] += v;
        __syncthreads();
    }
    int base = s[t] - sum;
    #pragma unroll
    for (int i = 0; i < 4; i++) { g_rowptr[t * 4 + i] = base; base += c[i]; }
    if (t == 1023) g_rowptr[N_INST] = base;
}

// ---------------- CSR index fill ----------------
__global__ __launch_bounds__(256) void fill_kernel() {
    int warp = (blockIdx.x * 256 + threadIdx.x) >> 5;
    int lane = threadIdx.x & 31;
    if (warp >= N_INST) return;
    float thr2 = g_thr2[0];
    const float* d = &g_d2[(size_t)warp * N_INST];
    int base = g_rowptr[warp];
    for (int j0 = 0; j0 < N_INST; j0 += 32) {
        int j = j0 + lane;
        bool p = (d[j] < thr2) && (j != warp);
        unsigned int m = __ballot_sync(0xffffffffu, p);
        if (p) {
            int pos = __popc(m & ((1u << lane) - 1u));
            g_idx[base + pos] = j;
        }
        base += __popc(m);
    }
}

// ---------------- sparse AH = A @ H ----------------
__global__ __launch_bounds__(128) void spmm_kernel() {
    int row = blockIdx.x;
    int f4 = threadIdx.x;
    if (f4 >= 125) return;
    int s = g_rowptr[row], e = g_rowptr[row + 1];
    float4 acc = make_float4(0.f, 0.f, 0.f, 0.f);
    const float4* H4 = (const float4*)g_H;
    for (int i = s; i < e; i++) {
        int j = g_idx[i];
        float4 v = H4[(size_t)j * 125 + f4];
        acc.x += v.x; acc.y += v.y; acc.z += v.z; acc.w += v.w;
    }
    ((float4*)g_AH)[(size_t)row * 125 + f4] = acc;
}

// ---------------- BN stats / finish ----------------
__global__ __launch_bounds__(512) void bnstats_kernel() {
    int f = threadIdx.x;
    if (f >= LF) return;
    int r0 = blockIdx.x * 128;
    float s = 0.f, q = 0.f;
    for (int r = 0; r < 128; r++) {
        float v = g_Zl[(size_t)(r0 + r) * LF + f];
        s += v; q += v * v;
    }
    atomicAdd(&g_bnsum[f], s);
    atomicAdd(&g_bnsq[f], q);
}
__global__ void bnfinish_kernel(const float* __restrict__ bng, const float* __restrict__ bnb) {
    int f = blockIdx.x * blockDim.x + threadIdx.x;
    if (f >= LF) return;
    float m = g_bnsum[f] * (1.f / (float)N_INST);
    float var = g_bnsq[f] * (1.f / (float)N_INST) - m * m;
    float a = bng[f] * rsqrtf(var + 1e-5f);
    g_bna[f] = a;
    g_bnbs[f] = bnb[f] - m * a;
}

// ---------------- soft assignment S ----------------
__global__ __launch_bounds__(256) void s_kernel(const float* __restrict__ wout,
    const float* __restrict__ bout, const float* __restrict__ wroot) {
    int warp = (blockIdx.x * 256 + threadIdx.x) >> 5;
    int lane = threadIdx.x & 31;
    if (warp >= N_INST) return;
    const float* ah = &g_AH[(size_t)warp * LF];
    const float* h  = &g_H[(size_t)warp * LF];
    float r1 = g_rs1[warp];
    float acc[CC] = {0.f, 0.f, 0.f, 0.f, 0.f};
    for (int k = lane; k < LF; k += 32) {
        float hv = h[k];
        float a = (ah[k] + hv) * r1;
        #pragma unroll
        for (int c = 0; c < CC; c++)
            acc[c] += a * wout[c * LF + k] + hv * wroot[c * LF + k];
    }
    #pragma unroll
    for (int c = 0; c < CC; c++)
        #pragma unroll
        for (int o = 16; o > 0; o >>= 1)
            acc[c] += __shfl_xor_sync(0xffffffffu, acc[c], o);
    if (!lane) {
        float t[CC], m = -1e30f;
        #pragma unroll
        for (int c = 0; c < CC; c++) { t[c] = acc[c] + bout[c]; m = fmaxf(m, t[c]); }
        float s = 0.f;
        #pragma unroll
        for (int c = 0; c < CC; c++) { t[c] = expf(t[c] - m); s += t[c]; }
        float inv = 1.f / s;
        #pragma unroll
        for (int c = 0; c < CC; c++) g_S[warp * CC + c] = t[c] * inv;
    }
}

// ---------------- AS = A @ S (CSR) ----------------
__global__ __launch_bounds__(256) void as_kernel() {
    int warp = (blockIdx.x * 256 + threadIdx.x) >> 5;
    int lane = threadIdx.x & 31;
    if (warp >= N_INST) return;
    int s = g_rowptr[warp], e = g_rowptr[warp + 1];
    float acc[CC] = {0.f, 0.f, 0.f, 0.f, 0.f};
    for (int i = s + lane; i < e; i += 32) {
        int j = g_idx[i];
        const float* sp = &g_S[j * CC];
        #pragma unroll
        for (int c = 0; c < CC; c++) acc[c] += sp[c];
    }
    #pragma unroll
    for (int c = 0; c < CC; c++)
        #pragma unroll
        for (int o = 16; o > 0; o >>= 1)
            acc[c] += __shfl_xor_sync(0xffffffffu, acc[c], o);
    if (!lane)
        #pragma unroll
        for (int c = 0; c < CC; c++) g_AS[warp * CC + c] = acc[c];
}

// ---------------- coar = S^T @ Z with BN folded ----------------
__global__ __launch_bounds__(128) void coar_kernel() {
    __shared__ float ss[256 * CC];
    int f = blockIdx.x * 128 + threadIdx.x;
    float acc[CC] = {0.f, 0.f, 0.f, 0.f, 0.f};
    float ssum[CC] = {0.f, 0.f, 0.f, 0.f, 0.f};
    for (int r0 = 0; r0 < N_INST; r0 += 256) {
        for (int i = threadIdx.x; i < 256 * CC; i += 128) ss[i] = g_S[r0 * CC + i];
        __syncthreads();
        if (f < LF) {
            for (int r = 0; r < 256; r++) {
                float z = g_Zl[(size_t)(r0 + r) * LF + f];
                #pragma unroll
                for (int c = 0; c < CC; c++) {
                    acc[c] += ss[r * CC + c] * z;
                    ssum[c] += ss[r * CC + c];
                }
            }
        }
        __syncthreads();
    }
    if (f < LF) {
        float a = g_bna[f], b = g_bnbs[f];
        #pragma unroll
        for (int c = 0; c < CC; c++) g_coar[c * LF + f] = a * acc[c] + b * ssum[c];
    }
}

// ---------------- Ac = S^T @ AS ----------------
__global__ __launch_bounds__(256) void ac_kernel() {
    __shared__ float sAc[CC * CC];
    int tid = threadIdx.x;
    if (tid < CC * CC) sAc[tid] = 0.f;
    __syncthreads();
    float acc[CC * CC];
    #pragma unroll
    for (int i = 0; i < CC * CC; i++) acc[i] = 0.f;
    for (int r = tid; r < N_INST; r += 256) {
        float sv[CC], av[CC];
        #pragma unroll
        for (int c = 0; c < CC; c++) { sv[c] = g_S[r * CC + c]; av[c] = g_AS[r * CC + c]; }
        #pragma unroll
        for (int c1 = 0; c1 < CC; c1++)
            #pragma unroll
            for (int c2 = 0; c2 < CC; c2++)
                acc[c1 * CC + c2] += sv[c1] * av[c2];
    }
    #pragma unroll
    for (int i = 0; i < CC * CC; i++) atomicAdd(&sAc[i], acc[i]);
    __syncthreads();
    if (tid < CC * CC) g_Ac[tid] = sAc[tid];
}

// ---------------- Mc / coarse degrees ----------------
__global__ void mc_kernel() {
    if (threadIdx.x == 0 && blockIdx.x == 0) {
        float s = 0.f;
        for (int i = 0; i < CC * CC; i++) s += g_Ac[i];
        float mean = s * (1.f / (float)(CC * CC));
        for (int c = 0; c < CC; c++) {
            float dg = 0.f;
            for (int j = 0; j < CC; j++) {
                float a = g_Ac[c * CC + j];
                float m = (a >= mean && a > 0.f) ? 1.f : 0.f;
                g_Mc[c * CC + j] = m;
                dg += m;
            }
            g_invdegc[c] = 1.f / fmaxf(dg, 1.f);
        }
    }
}

// ---------------- neigh = (Mc @ coar)/deg ----------------
__global__ void neigh_kernel() {
    int f = blockIdx.x * blockDim.x + threadIdx.x;
    if (f >= LF) return;
    #pragma unroll
    for (int c = 0; c < CC; c++) {
        float s = 0.f;
        #pragma unroll
        for (int j = 0; j < CC; j++) s += g_Mc[c * CC + j] * g_coar[j * LF + f];
        g_neigh[c * LF + f] = s * g_invdegc[c];
    }
}

// ---------------- coarse SAGE + leaky ----------------
__global__ __launch_bounds__(256) void csage_kernel(const float* __restrict__ wl,
    const float* __restrict__ bl, const float* __restrict__ wr) {
    int idx = blockIdx.x * 256 + threadIdx.x;
    if (idx >= CC * LF) return;
    int c = idx / LF, f = idx % LF;
    float acc = bl[f];
    const float* ng = &g_neigh[c * LF];
    const float* cr = &g_coar[c * LF];
    const float* wlr = &wl[f * LF];
    const float* wrr = &wr[f * LF];
    for (int k = 0; k < LF; k++)
        acc += ng[k] * wlr[k] + cr[k] * wrr[k];
    g_E[idx] = acc > 0.f ? acc : 0.01f * acc;
}

// ---------------- coarse BN + neighbor max-pool ----------------
__global__ __launch_bounds__(512) void cbnpool_kernel(const float* __restrict__ bng,
                                                      const float* __restrict__ bnb) {
    int f = threadIdx.x;
    if (f >= LF) return;
    float v[CC], s = 0.f;
    #pragma unroll
    for (int c = 0; c < CC; c++) { v[c] = g_E[c * LF + f]; s += v[c]; }
    float m = s * (1.f / (float)CC);
    float var = 0.f;
    #pragma unroll
    for (int c = 0; c < CC; c++) { float d = v[c] - m; var += d * d; }
    var *= (1.f / (float)CC);
    float a = bng[f] * rsqrtf(var + 1e-5f);
    float z[CC];
    #pragma unroll
    for (int c = 0; c < CC; c++) z[c] = (v[c] - m) * a + bnb[f];
    #pragma unroll
    for (int c = 0; c < CC; c++) {
        float p = -1e30f;
        #pragma unroll
        for (int j = 0; j < CC; j++) {
            bool mk = (c == j) || (g_Mc[c * CC + j] > 0.f);
            if (mk) p = fmaxf(p, z[j]);
        }
        g_pooled[c * LF + f] = p;
    }
}

// ---------------- MLP head + softmax + output ----------------
__global__ __launch_bounds__(256) void mlp_kernel(const float* __restrict__ w1,
    const float* __restrict__ b1, const float* __restrict__ w2,
    const float* __restrict__ b2, float* __restrict__ out, int out_size) {
    __shared__ float h1[CC * 250];
    __shared__ float lg[CC];
    int tid = threadIdx.x;
    for (int idx = tid; idx < CC * 250; idx += 256) {
        int c = idx / 250, j = idx % 250;
        float acc = b1[j];
        const float* p = &g_pooled[c * LF];
        const float* wr = &w1[j * LF];
        for (int k = 0; k < LF; k++) acc += p[k] * wr[k];
        h1[idx] = acc > 0.f ? acc : 0.01f * acc;
    }
    __syncthreads();
    if (tid < CC) {
        float acc = b2[0];
        for (int j = 0; j < 250; j++) acc += h1[tid * 250 + j] * w2[j];
        lg[tid] = acc > 0.f ? acc : 0.01f * acc;
    }
    __syncthreads();
    if (tid == 0) {
        float m = -1e30f;
        for (int c = 0; c < CC; c++) m = fmaxf(m, lg[c]);
        float s = 0.f, e[CC];
        for (int c = 0; c < CC; c++) { e[c] = expf(lg[c] - m); s += e[c]; }
        float p = 0.f;
        for (int c = 0; c < CC; c++) p = fmaxf(p, e[c] / s);
        out[0] = p;
        if (out_size > 1) out[1] = (p >= 0.5f) ? 1.f : 0.f;
    }
}

// ---------------- host ----------------
extern "C" void kernel_launch(void* const* d_in, const int* in_sizes, int n_in,
                              void* d_out, int out_size) {
    const float* x       = (const float*)d_in[0];
    const float* conv1_w = (const float*)d_in[1];
    const float* conv1_b = (const float*)d_in[2];
    const float* conv2_w = (const float*)d_in[3];
    const float* conv2_b = (const float*)d_in[4];
    const float* fc_w    = (const float*)d_in[5];
    const float* fc_b    = (const float*)d_in[6];
    const float* sage_wl = (const float*)d_in[7];
    const float* sage_bl = (const float*)d_in[8];
    const float* sage_wr = (const float*)d_in[9];
    const float* bn_g    = (const float*)d_in[10];
    const float* bn_b    = (const float*)d_in[11];
    const float* cg_wout = (const float*)d_in[12];
    const float* cg_bout = (const float*)d_in[13];
    const float* cg_wroot= (const float*)d_in[14];
    const float* lin1_w  = (const float*)d_in[15];
    const float* lin1_b  = (const float*)d_in[16];
    const float* lin2_w  = (const float*)d_in[17];
    const float* lin2_b  = (const float*)d_in[18];
    float* out = (float*)d_out;

    float *pP2, *pH, *pAH, *pZl, *pRS;
    float *pP2hi, *pP2lo, *pfwhi, *pfwlo, *pXhi, *pXlo;
    float *pwlhi, *pwllo, *pwrhi, *pwrlo, *pHhi, *pHlo;
    cudaGetSymbolAddress((void**)&pP2, g_P2);
    cudaGetSymbolAddress((void**)&pH,  g_H);
    cudaGetSymbolAddress((void**)&pAH, g_AH);
    cudaGetSymbolAddress((void**)&pZl, g_Zl);
    cudaGetSymbolAddress((void**)&pRS, g_rs);
    cudaGetSymbolAddress((void**)&pP2hi, g_P2hi);
    cudaGetSymbolAddress((void**)&pP2lo, g_P2lo);
    cudaGetSymbolAddress((void**)&pfwhi, g_fwhi);
    cudaGetSymbolAddress((void**)&pfwlo, g_fwlo);
    cudaGetSymbolAddress((void**)&pXhi, g_Xhi);
    cudaGetSymbolAddress((void**)&pXlo, g_Xlo);
    cudaGetSymbolAddress((void**)&pwlhi, g_wlhi);
    cudaGetSymbolAddress((void**)&pwllo, g_wllo);
    cudaGetSymbolAddress((void**)&pwrhi, g_wrhi);
    cudaGetSymbolAddress((void**)&pwrlo, g_wrlo);
    cudaGetSymbolAddress((void**)&pHhi, g_Hhi);
    cudaGetSymbolAddress((void**)&pHlo, g_Hlo);

    cudaFuncSetAttribute(gram_mma_kernel,
                         cudaFuncAttributeMaxDynamicSharedMemorySize, GRAM_SMEM);
    cudaFuncSetAttribute(gemm_ps<false, 1>,
                         cudaFuncAttributeMaxDynamicSharedMemorySize, GRAM_SMEM);
    cudaFuncSetAttribute(gemm_ps<true, 2>,
                         cudaFuncAttributeMaxDynamicSharedMemorySize, GRAM_SMEM);

    init_kernel<<<1, 512>>>();
    conv1_kernel<<<N_INST, 512>>>(x, conv1_w, conv1_b);
    conv2_kernel<<<N_INST, 256>>>(conv2_w, conv2_b);

    // pre-split FC operands (weights split can overlap; data split after conv2)
    splitg_kernel<<<(512*800 + 255)/256, 256>>>(fc_w, pfwhi, pfwlo, 512, LF, 800, 800, 800, nullptr);
    splitg_kernel<<<(N_INST*800 + 255)/256, 256>>>(pP2, pP2hi, pP2lo, N_INST, N_INST, 800, 800, 800, nullptr);

    // FC: H = relu(P2 @ fc_w^T + fc_b) via pre-split 3xTF32 mma
    gemm_ps<false, 1><<<dim3(4, 32), 256, GRAM_SMEM>>>(
        pP2hi, pP2lo, pfwhi, pfwlo, nullptr, nullptr, nullptr, nullptr,
        pH, N_INST, LF, 800, LF, fc_b);

    split_kernel<<<(N_INST * (KPAD/4) + 255) / 256, 256>>>();
    sq_kernel<<<512, 256>>>();

    // d2 via 3xTF32 mma.sync Gram (symmetric, mirrored)
    gram_mma_kernel<<<dim3(32, 32), 256, GRAM_SMEM>>>();

    hist_kernel<<<N_INST, 256>>>();
    select_thr_kernel<<<1, 32>>>();
    deg_kernel<<<512, 256>>>();
    scan_kernel<<<1, 1024>>>();
    fill_kernel<<<512, 256>>>();
    spmm_kernel<<<N_INST, 128>>>();

    // pre-split SAGE operands: X = rs*AH (rowscale fused), wl, wr; H reused from gram split
    splitg_kernel<<<(512*512 + 255)/256, 256>>>(sage_wl, pwlhi, pwllo, 512, LF, LF, LF, 512, nullptr);
    splitg_kernel<<<(512*512 + 255)/256, 256>>>(sage_wr, pwrhi, pwrlo, 512, LF, LF, LF, 512, nullptr);
    splitg_kernel<<<(N_INST*KPAD + 255)/256, 256>>>(pAH, pXhi, pXlo, N_INST, N_INST, LF, LF, KPAD, pRS);

    // Fused SAGE: Zl = leaky((rs*AH) @ wl^T + bl + H @ wr^T)
    gemm_ps<true, 2><<<dim3(4, 32), 256, GRAM_SMEM>>>(
        pXhi, pXlo, pwlhi, pwllo, pHhi, pHlo, pwrhi, pwrlo,
        pZl, N_INST, LF, KPAD, LF, sage_bl);

    bnstats_kernel<<<32, 512>>>();
    bnfinish_kernel<<<1, 512>>>(bn_g, bn_b);

    s_kernel<<<512, 256>>>(cg_wout, cg_bout, cg_wroot);
    as_kernel<<<512, 256>>>();
    coar_kernel<<<4, 128>>>();
    ac_kernel<<<1, 256>>>();
    mc_kernel<<<1, 32>>>();
    neigh_kernel<<<1, 512>>>();
    csage_kernel<<<10, 256>>>(sage_wl, sage_bl, sage_wr);
    cbnpool_kernel<<<1, 512>>>(bn_g, bn_b);
    mlp_kernel<<<1, 256>>>(lin1_w, lin1_b, lin2_w, lin2_b, out, out_size);
}